// round 7
// baseline (speedup 1.0000x reference)
#include <cuda_runtime.h>

// ---------------- problem constants ----------------
#define NB 1024
#define NT 128
#define ND 256
#define NH 128
#define NG 512
#define NK 640
#define KSPLIT 2
#define KPER (NK / KSPLIT)     // 320
#define NSLAB (KPER / 32)      // 10
#define NCTA 128

typedef unsigned long long ull;
typedef ulonglong2 ull2;

// ---------------- f32x2 packed math ----------------
__device__ __forceinline__ ull ffma2(ull a, ull b, ull c) {
    ull d;
    asm("fma.rn.f32x2 %0, %1, %2, %3;" : "=l"(d) : "l"(a), "l"(b), "l"(c));
    return d;
}
__device__ __forceinline__ float2 unpack2(ull v) {
    float2 r; asm("mov.b64 {%0, %1}, %2;" : "=f"(r.x), "=f"(r.y) : "l"(v)); return r;
}
__device__ __forceinline__ float sig_fast(float x) { return 1.0f / (1.0f + __expf(-x)); }
__device__ __forceinline__ float tanh_fast(float x) { return 2.0f / (1.0f + __expf(-2.0f * x)) - 1.0f; }

__device__ __forceinline__ unsigned smem_u32(const void* p) {
    unsigned r;
    asm("{ .reg .u64 t; cvta.to.shared.u64 t, %1; cvt.u32.u64 %0, t; }" : "=r"(r) : "l"(p));
    return r;
}
#define CP16(dst, src) asm volatile("cp.async.cg.shared.global [%0], [%1], 16;" :: "r"(dst), "l"(src))
#define CP_COMMIT()    asm volatile("cp.async.commit_group;")
#define CP_WAIT1()     asm volatile("cp.async.wait_group 1;")
#define CP_WAIT0()     asm volatile("cp.async.wait_group 0;")

// ---------------- device scratch ----------------
__device__ float g_pre[(size_t)NT * NB * NG];   // [t*NB+b][rr] gate-reordered
__device__ float g_Wro[NG * NK];                // row rr=4u+gate, cols [W_hh | A_0..A_3]
__device__ float g_Wxro[NG * ND];               // reordered x-part of W_ih
__device__ float g_part[KSPLIT][(size_t)NB * NG];
__device__ float g_memsm[NH * NH];
__device__ float g_fA[2 * NK];
__device__ float g_h[2][NB * NH];
__device__ float g_c[NB * NH];
__device__ float g_hsum[NB * NH];
__device__ float g_biasro[NG];
__device__ float g_c0ro[NG];
__device__ unsigned g_arrive;
__device__ unsigned g_gen;

// ---------------- grid barrier (sense-reversing) ----------------
__device__ __forceinline__ void grid_barrier() {
    __syncthreads();
    if (threadIdx.x == 0) {
        __threadfence();
        unsigned gen = *(volatile unsigned*)&g_gen;
        unsigned t = atomicAdd(&g_arrive, 1u);
        if (t == (unsigned)(gridDim.x - 1)) {
            g_arrive = 0;
            __threadfence();
            *(volatile unsigned*)&g_gen = gen + 1;
        } else {
            while (*(volatile unsigned*)&g_gen == gen) { __nanosleep(64); }
        }
        __threadfence();
    }
    __syncthreads();
}

// ---------------- 8x4 f32x2 tile over one 32-k slab ----------------
// A: row r, quad qn at r*128 + ((qn ^ permA(r))<<4), permA(r)=(r^(r>>3))&7
// B: col c, quad (slab-local) at c*BSTRIDE + slabbase + ((qn ^ permB(c))<<4)
template <int BSTRIDE>
__device__ __forceinline__ void slab84(const char* Ab, const char* Bb,
                                       const int aoff[8], const int boff[4],
                                       ull* acc /*32*/) {
    #pragma unroll
    for (int q = 0; q < 8; q++) {
        ull2 b[4];
        #pragma unroll
        for (int j = 0; j < 4; j++)
            b[j] = *(const ull2*)(Bb + (boff[j] ^ (q << 4)));
        #pragma unroll
        for (int i = 0; i < 8; i++) {
            ull2 a = *(const ull2*)(Ab + (aoff[i] ^ (q << 4)));
            #pragma unroll
            for (int j = 0; j < 4; j++) {
                acc[i * 4 + j] = ffma2(a.x, b[j].x, acc[i * 4 + j]);
                acc[i * 4 + j] = ffma2(a.y, b[j].y, acc[i * 4 + j]);
            }
        }
    }
}

// ---------------- setup: softmax, reordered bias/const0 ----------------
__global__ void setup_kernel(const float* __restrict__ memory,
                             const float* __restrict__ b_ih,
                             const float* __restrict__ b_hh,
                             const float* __restrict__ rv0,
                             const float* __restrict__ W_ih) {
    int tid = threadIdx.x;
    float mx = -1e30f;
    for (int m = 0; m < NH; m++) mx = fmaxf(mx, memory[m * NH + tid]);
    float s = 0.f;
    for (int m = 0; m < NH; m++) s += expf(memory[m * NH + tid] - mx);
    float inv = 1.f / s;
    for (int m = 0; m < NH; m++)
        g_memsm[m * NH + tid] = expf(memory[m * NH + tid] - mx) * inv;

    for (int g = tid; g < NG; g += 128) {
        int u = g & 127, gate = g >> 7;
        int rr = 4 * u + gate;
        g_biasro[rr] = b_ih[g] + b_hh[g];
        float c0 = 0.f;
        const float* w = W_ih + (size_t)g * 768 + 256;
        for (int k = 0; k < 512; k++) c0 += rv0[k] * w[k];
        g_c0ro[rr] = c0;
    }
}

// ---------------- fold mem_sm into weights (reordered rows) ----------------
__global__ void buildA_kernel(const float* __restrict__ W_ih,
                              const float* __restrict__ W_hh,
                              const float* __restrict__ fc_w) {
    int row = blockIdx.x, q = blockIdx.y, j = threadIdx.x;
    if (row < NG) {
        int u = row >> 2, gate = row & 3;
        int go = gate * 128 + u;
        if (q == 0) {
            g_Wro[(size_t)row * NK + j] = W_hh[(size_t)go * NH + j];
        } else {
            const float* w = W_ih + (size_t)go * 768 + 256 + (q - 1) * 128;
            float s = 0.f;
            for (int m = 0; m < NH; m++) s += w[m] * g_memsm[m * NH + j];
            g_Wro[(size_t)row * NK + q * 128 + j] = s;
        }
    } else {
        int o = row - NG;
        if (q == 0) {
            g_fA[o * NK + j] = fc_w[o * NK + j];
        } else {
            const float* w = fc_w + o * NK + 128 + (q - 1) * 128;
            float s = 0.f;
            for (int m = 0; m < NH; m++) s += w[m] * g_memsm[m * NH + j];
            g_fA[o * NK + q * 128 + j] = s;
        }
    }
}

__global__ void buildX_kernel(const float* __restrict__ W_ih) {
    int row = blockIdx.x;   // rr
    int q   = blockIdx.y;
    int j   = threadIdx.x;
    int u = row >> 2, gate = row & 3;
    int go = gate * 128 + u;
    g_Wxro[(size_t)row * ND + q * 128 + j] = W_ih[(size_t)go * 768 + q * 128 + j];
}

// ---------------- pre: [NT*NB,256] x [256,512] -> g_pre ----------------
__global__ __launch_bounds__(256)
void pre_kernel(const float* __restrict__ x) {
    extern __shared__ char smc[];   // 3 stages x (A 16KB + B 8KB) = 72KB
    int r0  = blockIdx.x * 128;
    int rr0 = blockIdx.y * 64;
    int tid = threadIdx.x;
    int tx = tid & 15, ty = tid >> 4;

    // fill mappings
    int arow = tid >> 1;
    int aq0 = (tid & 1) * 4;
    int aperm = (arow ^ (arow >> 3)) & 7;
    int bcol = tid >> 2;
    int bq0 = (tid & 3) * 2;
    int bperm = (bcol ^ (bcol >> 3)) & 7;

    int rA = r0 + arow;
    int bb = rA & 1023, tA = rA >> 10;
    const float* xrow = x + ((size_t)bb * NT + tA) * ND;
    const float* wrow = g_Wxro + (size_t)(rr0 + bcol) * ND;
    unsigned smem_base = smem_u32(smc);

    #define PRE_ISSUE(s)                                                        \
    {                                                                           \
        unsigned stg = smem_base + ((s) % 3) * 24576u;                          \
        unsigned ab  = stg + (unsigned)(arow * 128);                            \
        unsigned bbs = stg + 16384u + (unsigned)(bcol * 128);                   \
        const float* ap = xrow + (s) * 32;                                      \
        const float* bp = wrow + (s) * 32;                                      \
        _Pragma("unroll")                                                       \
        for (int p = 0; p < 4; p++) { int qn = aq0 + p; CP16(ab + ((qn ^ aperm) << 4), ap + qn * 4); } \
        _Pragma("unroll")                                                       \
        for (int p = 0; p < 2; p++) { int qn = bq0 + p; CP16(bbs + ((qn ^ bperm) << 4), bp + qn * 4); } \
        CP_COMMIT();                                                            \
    }

    int aoff[8], boff[4];
    #pragma unroll
    for (int i = 0; i < 8; i++)
        aoff[i] = ((ty * 8 + i) * 128) ^ ((((ty ^ i) & 7)) << 4);
    #pragma unroll
    for (int j = 0; j < 4; j++) {
        int cc = tx * 4 + j;
        boff[j] = (cc * 128) ^ ((((cc ^ (cc >> 3)) & 7)) << 4);
    }

    ull acc[32];
    #pragma unroll
    for (int i = 0; i < 32; i++) acc[i] = 0ull;

    const int NS = ND / 32;   // 8
    PRE_ISSUE(0);
    PRE_ISSUE(1);
    for (int s = 0; s < NS; s++) {
        if (s + 2 < NS) { CP_WAIT1(); } else { CP_WAIT0(); }
        __syncthreads();
        if (s + 2 < NS) PRE_ISSUE(s + 2);
        const char* Ab = smc + (s % 3) * 24576;
        slab84<128>(Ab, Ab + 16384, aoff, boff, acc);
        __syncthreads();
    }
    #undef PRE_ISSUE

    int tt = r0 >> 10;
    #pragma unroll
    for (int i = 0; i < 8; i++) {
        int r = r0 + ty * 8 + i;
        int rr = rr0 + tx * 4;
        float2 s0 = unpack2(acc[i * 4 + 0]);
        float2 s1 = unpack2(acc[i * 4 + 1]);
        float2 s2 = unpack2(acc[i * 4 + 2]);
        float2 s3 = unpack2(acc[i * 4 + 3]);
        float4 v;
        v.x = s0.x + s0.y + g_biasro[rr];
        v.y = s1.x + s1.y + g_biasro[rr + 1];
        v.z = s2.x + s2.y + g_biasro[rr + 2];
        v.w = s3.x + s3.y + g_biasro[rr + 3];
        if (tt == 0) {
            v.x += g_c0ro[rr];     v.y += g_c0ro[rr + 1];
            v.z += g_c0ro[rr + 2]; v.w += g_c0ro[rr + 3];
        }
        *(float4*)(g_pre + (size_t)r * NG + rr) = v;
    }
}

// ---------------- persistent recurrence kernel ----------------
__global__ __launch_bounds__(256)
void recur_kernel() {
    extern __shared__ char smc[];   // Bres 80KB + 3 A-stages x 16KB = 128KB
    char* Bres = smc;
    char* Ast  = smc + 81920;

    int tid = threadIdx.x;
    int cta = blockIdx.x;
    int sp = cta & 1;
    int tile = cta >> 1;
    int b0  = (tile & 7) << 7;      // 8 batch tiles of 128
    int rr0 = (tile >> 3) << 6;     // 8 gate tiles of 64
    int tx = tid & 15, ty = tid >> 4;

    // zero h0/c/hsum slice
    {
        int idx = cta * 1024 + tid * 4;
        float4 z = make_float4(0.f, 0.f, 0.f, 0.f);
        *(float4*)(g_h[0] + idx) = z;
        *(float4*)(g_c + idx) = z;
        *(float4*)(g_hsum + idx) = z;
    }

    // load resident B tile: 64 cols x 80 quads (KPER=320)
    {
        unsigned bb = smem_u32(Bres);
        for (int idx = tid; idx < 64 * 80; idx += 256) {
            int c = idx / 80, gq = idx % 80;
            int perm = (c ^ (c >> 3)) & 7;
            int dq = c * 80 + ((gq & ~7) | ((gq & 7) ^ perm));
            CP16(bb + ((unsigned)dq << 4),
                 g_Wro + (size_t)(rr0 + c) * NK + sp * KPER + gq * 4);
        }
        CP_COMMIT(); CP_WAIT0();
    }
    grid_barrier();

    // fill-side constants
    int arow = tid >> 1;
    int aq0 = (tid & 1) * 4;
    int aperm = (arow ^ (arow >> 3)) & 7;
    int bA = b0 + arow;
    unsigned asm_base = smem_u32(Ast) + (unsigned)(arow * 128);

    int aoff[8], boff[4];
    #pragma unroll
    for (int i = 0; i < 8; i++)
        aoff[i] = ((ty * 8 + i) * 128) ^ ((((ty ^ i) & 7)) << 4);
    #pragma unroll
    for (int j = 0; j < 4; j++) {
        int cc = tx * 4 + j;
        boff[j] = (cc * 1280) ^ ((((cc ^ (cc >> 3)) & 7)) << 4);
    }

    // LSTM-phase mapping
    int lb = cta * 8 + (tid >> 5);
    int u0 = (tid & 31) * 4;

    for (int t = 0; t < NT; t++) {
        const float* __restrict__ Hp = g_h[t & 1];

        #define REC_ISSUE(s)                                                    \
        {                                                                       \
            int k0 = sp * KPER + (s) * 32;                                      \
            int src, col;                                                       \
            if (k0 < 128) { src = bA; col = k0; }                               \
            else { int qd = (k0 - 128) >> 7; src = (4 * bA + qd) & 1023; col = (k0 - 128) & 127; } \
            const float* ap = Hp + src * NH + col;                              \
            unsigned abase = asm_base + ((s) % 3) * 16384u;                     \
            _Pragma("unroll")                                                   \
            for (int p = 0; p < 4; p++) {                                       \
                int qn = aq0 + p;                                               \
                CP16(abase + ((qn ^ aperm) << 4), ap + qn * 4);                 \
            }                                                                   \
            CP_COMMIT();                                                        \
        }

        ull acc[32];
        #pragma unroll
        for (int i = 0; i < 32; i++) acc[i] = 0ull;

        REC_ISSUE(0);
        REC_ISSUE(1);
        for (int s = 0; s < NSLAB; s++) {
            if (s + 2 < NSLAB) { CP_WAIT1(); } else { CP_WAIT0(); }
            __syncthreads();
            if (s + 2 < NSLAB) REC_ISSUE(s + 2);
            slab84<1280>(Ast + (s % 3) * 16384, Bres + s * 128, aoff, boff, acc);
            __syncthreads();
        }
        #undef REC_ISSUE

        // store partials
        {
            float* P = g_part[sp];
            #pragma unroll
            for (int i = 0; i < 8; i++) {
                int b = b0 + ty * 8 + i;
                float2 s0 = unpack2(acc[i * 4 + 0]);
                float2 s1 = unpack2(acc[i * 4 + 1]);
                float2 s2 = unpack2(acc[i * 4 + 2]);
                float2 s3 = unpack2(acc[i * 4 + 3]);
                float4 v = make_float4(s0.x + s0.y, s1.x + s1.y,
                                       s2.x + s2.y, s3.x + s3.y);
                *(float4*)(P + (size_t)b * NG + rr0 + tx * 4) = v;
            }
        }
        grid_barrier();

        // LSTM pointwise: 4 cells per thread
        {
            const float4* P0 = (const float4*)(g_part[0] + (size_t)lb * NG + 4 * u0);
            const float4* P1 = (const float4*)(g_part[1] + (size_t)lb * NG + 4 * u0);
            const float4* PR = (const float4*)(g_pre + ((size_t)t * NB + lb) * NG + 4 * u0);
            int cidx = lb * NH + u0;
            float4 cold = *(float4*)(g_c + cidx);
            float4 hs   = *(float4*)(g_hsum + cidx);
            float cn[4], hn[4];
            float co[4] = {cold.x, cold.y, cold.z, cold.w};
            #pragma unroll
            for (int du = 0; du < 4; du++) {
                float4 a = P0[du], b = P1[du], p = PR[du];
                float gi = a.x + b.x + p.x;
                float gf = a.y + b.y + p.y;
                float gg = a.z + b.z + p.z;
                float go = a.w + b.w + p.w;
                float cv = sig_fast(gf) * co[du] + sig_fast(gi) * tanh_fast(gg);
                cn[du] = cv;
                hn[du] = sig_fast(go) * tanh_fast(cv);
            }
            *(float4*)(g_c + cidx) = make_float4(cn[0], cn[1], cn[2], cn[3]);
            *(float4*)(g_h[(t + 1) & 1] + cidx) = make_float4(hn[0], hn[1], hn[2], hn[3]);
            *(float4*)(g_hsum + cidx) = make_float4(hs.x + hn[0], hs.y + hn[1],
                                                    hs.z + hn[2], hs.w + hn[3]);
        }
        grid_barrier();
    }
}

// ---------------- final ----------------
__global__ void final_kernel(float* __restrict__ out, const float* __restrict__ fc_b) {
    int b = blockIdx.x * blockDim.x + threadIdx.x;
    if (b >= NB) return;
    #pragma unroll
    for (int o = 0; o < 2; o++) {
        const float* f = g_fA + o * NK;
        const float* hs = g_hsum + b * NH;
        float s = 0.f;
        for (int k = 0; k < NH; k++) s += f[k] * hs[k];
        #pragma unroll
        for (int q = 0; q < 4; q++) {
            const float* hq = g_hsum + ((4 * b + q) & 1023) * NH;
            const float* fq = f + 128 + q * 128;
            for (int m = 0; m < NH; m++) s += fq[m] * hq[m];
        }
        out[b * 2 + o] = fc_b[o] + s * (1.f / (float)NT);
    }
}

// ---------------- launch ----------------
extern "C" void kernel_launch(void* const* d_in, const int* in_sizes, int n_in,
                              void* d_out, int out_size) {
    const float* x      = (const float*)d_in[0];
    const float* memory = (const float*)d_in[1];
    const float* rv0    = (const float*)d_in[2];
    const float* W_ih   = (const float*)d_in[3];
    const float* W_hh   = (const float*)d_in[4];
    const float* b_ih   = (const float*)d_in[5];
    const float* b_hh   = (const float*)d_in[6];
    const float* fc_w   = (const float*)d_in[7];
    const float* fc_b   = (const float*)d_in[8];
    float* out = (float*)d_out;

    static bool attr_done = false;
    if (!attr_done) {
        cudaFuncSetAttribute(pre_kernel, cudaFuncAttributeMaxDynamicSharedMemorySize, 73728);
        cudaFuncSetAttribute(recur_kernel, cudaFuncAttributeMaxDynamicSharedMemorySize, 131072);
        attr_done = true;
    }

    setup_kernel<<<1, 128>>>(memory, b_ih, b_hh, rv0, W_ih);
    buildA_kernel<<<dim3(514, 5), 128>>>(W_ih, W_hh, fc_w);
    buildX_kernel<<<dim3(512, 2), 128>>>(W_ih);
    pre_kernel<<<dim3(NT * NB / 128, NG / 64), 256, 73728>>>(x);
    recur_kernel<<<NCTA, 256, 131072>>>();
    final_kernel<<<4, 256>>>(out, fc_b);
}